// round 3
// baseline (speedup 1.0000x reference)
#include <cuda_runtime.h>

// TrigoLinear: out[b,o] = sum_i sin(x[b,i]*w_sin[o,i] + b_sin[o,i]) * w_out[o,i] + b_out[o]
// Hybrid MUFU + packed-f32x2 Taylor-5. Tile 64x32, 256 thr, 2 CTAs/SM, grid 256.

#define B_DIM   1024
#define IN_DIM  512
#define OUT_DIM 512

#define BM 64
#define BN 32
#define BK 32
#define PADX 68   // sx row stride (floats), 16B-aligned rows
#define PADO 36   // o-side row stride

typedef unsigned long long ull;

__device__ __forceinline__ ull pk2(float lo, float hi) {
    ull d; asm("mov.b64 %0, {%1, %2};" : "=l"(d) : "f"(lo), "f"(hi)); return d;
}
__device__ __forceinline__ void upk2(ull d, float& lo, float& hi) {
    asm("mov.b64 {%0, %1}, %2;" : "=f"(lo), "=f"(hi) : "l"(d));
}
__device__ __forceinline__ ull fma2_(ull a, ull b, ull c) {
    ull d; asm("fma.rn.f32x2 %0, %1, %2, %3;" : "=l"(d) : "l"(a), "l"(b), "l"(c)); return d;
}
__device__ __forceinline__ ull mul2_(ull a, ull b) {
    ull d; asm("mul.rn.f32x2 %0, %1, %2;" : "=l"(d) : "l"(a), "l"(b)); return d;
}
__device__ __forceinline__ float sin_mufu(float a) {
    float d; asm("sin.approx.f32 %0, %1;" : "=f"(d) : "f"(a)); return d;
}

__global__ __launch_bounds__(256, 2)
void trigo_kernel(const float* __restrict__ x,
                  const float* __restrict__ weight,
                  const float* __restrict__ bias,
                  float* __restrict__ out) {
    __shared__ __align__(16) float sx [BK * PADX];  // [k][b]
    __shared__ __align__(16) float sws[BK * PADO];  // [k][o] w_sin
    __shared__ __align__(16) float sbs[BK * PADO];  // [k][o] b_sin
    __shared__ __align__(16) float swo[BK * PADO];  // [k][o] w_out

    const int tid = threadIdx.x;
    const int tx = tid & 15;   // 2 outs/thread: o = tx*2
    const int ty = tid >> 4;   // 4 rows/thread: b = ty*4
    const int bRow = blockIdx.y * BM;
    const int oCol = blockIdx.x * BN;

    const float2* __restrict__ w2 = (const float2*)weight;

    // register staging for software pipeline
    float  rx[8];
    float2 rw[4];
    float  rb[4];

    // prologue: tile 0
    #pragma unroll
    for (int j = 0; j < 8; j++) {
        int idx = tid + j * 256;
        rx[j] = x[(bRow + (idx >> 5)) * IN_DIM + (idx & 31)];
    }
    #pragma unroll
    for (int j = 0; j < 4; j++) {
        int idx = tid + j * 256;
        rw[j] = w2[(oCol + (idx >> 5)) * IN_DIM + (idx & 31)];
        rb[j] = bias[(oCol + (idx >> 5)) * (IN_DIM + 1) + (idx & 31)];
    }
    #pragma unroll
    for (int j = 0; j < 8; j++) {
        int idx = tid + j * 256;
        sx[(idx & 31) * PADX + (idx >> 5)] = rx[j];
    }
    #pragma unroll
    for (int j = 0; j < 4; j++) {
        int idx = tid + j * 256;
        int o = idx >> 5, k = idx & 31;
        swo[k * PADO + o] = rw[j].x;
        sws[k * PADO + o] = rw[j].y;
        sbs[k * PADO + o] = rb[j];
    }
    __syncthreads();

    const ull C3 = pk2(-1.6666667e-1f, -1.6666667e-1f);
    const ull C5 = pk2( 8.3333333e-3f,  8.3333333e-3f);

    ull acc[4] = {0ull, 0ull, 0ull, 0ull};  // [bb], each packs 2 outs

    for (int k0 = 0; k0 < IN_DIM; k0 += BK) {
        if (k0 + BK < IN_DIM) {
            #pragma unroll
            for (int j = 0; j < 8; j++) {
                int idx = tid + j * 256;
                rx[j] = x[(bRow + (idx >> 5)) * IN_DIM + k0 + BK + (idx & 31)];
            }
            #pragma unroll
            for (int j = 0; j < 4; j++) {
                int idx = tid + j * 256;
                rw[j] = w2[(oCol + (idx >> 5)) * IN_DIM + k0 + BK + (idx & 31)];
                rb[j] = bias[(oCol + (idx >> 5)) * (IN_DIM + 1) + k0 + BK + (idx & 31)];
            }
        }

        #pragma unroll 4
        for (int k = 0; k < BK; k++) {
            float4 xb = *(const float4*)&sx [k * PADX + ty * 4];
            float2 ws = *(const float2*)&sws[k * PADO + tx * 2];
            float2 bs = *(const float2*)&sbs[k * PADO + tx * 2];
            float2 wo = *(const float2*)&swo[k * PADO + tx * 2];

            ull wsp = pk2(ws.x, ws.y);
            ull bsp = pk2(bs.x, bs.y);
            ull wop = pk2(wo.x, wo.y);

            float xv[4] = {xb.x, xb.y, xb.z, xb.w};

            // bb 0,1 -> MUFU path
            #pragma unroll
            for (int bb = 0; bb < 2; bb++) {
                ull xd = pk2(xv[bb], xv[bb]);
                ull t = fma2_(xd, wsp, bsp);
                float l, h; upk2(t, l, h);
                l = sin_mufu(l);
                h = sin_mufu(h);
                acc[bb] = fma2_(pk2(l, h), wop, acc[bb]);
            }
            // bb 2,3 -> poly path: sin t = t + c3 t^3 + c5 t^5
            #pragma unroll
            for (int bb = 2; bb < 4; bb++) {
                ull xd = pk2(xv[bb], xv[bb]);
                ull t  = fma2_(xd, wsp, bsp);
                ull tt = mul2_(t, t);
                ull r  = fma2_(C5, tt, C3);
                r      = mul2_(r, tt);
                ull s  = fma2_(r, t, t);
                acc[bb] = fma2_(s, wop, acc[bb]);
            }
        }

        __syncthreads();
        if (k0 + BK < IN_DIM) {
            #pragma unroll
            for (int j = 0; j < 8; j++) {
                int idx = tid + j * 256;
                sx[(idx & 31) * PADX + (idx >> 5)] = rx[j];
            }
            #pragma unroll
            for (int j = 0; j < 4; j++) {
                int idx = tid + j * 256;
                int o = idx >> 5, k = idx & 31;
                swo[k * PADO + o] = rw[j].x;
                sws[k * PADO + o] = rw[j].y;
                sbs[k * PADO + o] = rb[j];
            }
            __syncthreads();
        }
    }

    // epilogue
    float bo0 = bias[(oCol + tx * 2 + 0) * (IN_DIM + 1) + IN_DIM];
    float bo1 = bias[(oCol + tx * 2 + 1) * (IN_DIM + 1) + IN_DIM];

    #pragma unroll
    for (int bb = 0; bb < 4; bb++) {
        float a0, a1;
        upk2(acc[bb], a0, a1);
        float2 v;
        v.x = a0 + bo0;
        v.y = a1 + bo1;
        *(float2*)&out[(bRow + ty * 4 + bb) * OUT_DIM + oCol + tx * 2] = v;
    }
}

extern "C" void kernel_launch(void* const* d_in, const int* in_sizes, int n_in,
                              void* d_out, int out_size) {
    const float* x      = (const float*)d_in[0];
    const float* weight = (const float*)d_in[1];
    const float* bias   = (const float*)d_in[2];
    float* out          = (float*)d_out;

    dim3 grid(OUT_DIM / BN, B_DIM / BM);  // (16, 16) = 256 CTAs
    trigo_kernel<<<grid, 256>>>(x, weight, bias, out);
}